// round 1
// baseline (speedup 1.0000x reference)
#include <cuda_runtime.h>
#include <cuda_bf16.h>
#include <cstdint>
#include <math.h>

// ---------------- problem constants ----------------
#define MTOK 8192      // B*S tokens
#define DIM  1024
#define NPAT 8192

// ---------------- scratch (static device arrays; no allocation) ----------------
__device__ __nv_bfloat16 g_xb  [(size_t)MTOK * DIM];    // x in bf16
__device__ __nv_bfloat16 g_wqb [(size_t)DIM * DIM];     // w_q in bf16 [out][in]
__device__ __nv_bfloat16 g_qb  [(size_t)MTOK * DIM];    // beta * q in bf16
__device__ __nv_bfloat16 g_xib [(size_t)NPAT * DIM];    // xi in bf16 [P][D]
__device__ __nv_bfloat16 g_xitb[(size_t)DIM * NPAT];    // xi^T in bf16 [D][P]
__device__ __nv_bfloat16 g_E   [(size_t)MTOK * NPAT];   // expm1(logits) in bf16 (128MB)
__device__ float g_colsum[DIM];                          // sum_p xi[p][d] (fp32)
__device__ float g_S[MTOK];                              // P + sum_p E[row][p]

// ---------------- small prep kernels ----------------
__global__ void cvt4_kernel(const float4* __restrict__ in, __nv_bfloat162* __restrict__ out, int n4) {
    int i = blockIdx.x * blockDim.x + threadIdx.x;
    if (i < n4) {
        float4 v = in[i];
        out[2 * i]     = __floats2bfloat162_rn(v.x, v.y);
        out[2 * i + 1] = __floats2bfloat162_rn(v.z, v.w);
    }
}

// xi -> bf16 [P][D] and transposed bf16 [D][P] via smem tiles
__global__ void xi_prep_kernel(const float* __restrict__ xi,
                               __nv_bfloat16* __restrict__ xib,
                               __nv_bfloat16* __restrict__ xitb) {
    __shared__ __nv_bfloat16 tile[32][33];
    int d0 = blockIdx.x * 32;
    int p0 = blockIdx.y * 32;
#pragma unroll
    for (int i = 0; i < 4; i++) {
        int p = p0 + threadIdx.y + i * 8;
        int d = d0 + threadIdx.x;
        float v = xi[(size_t)p * DIM + d];
        __nv_bfloat16 b = __float2bfloat16(v);
        xib[(size_t)p * DIM + d] = b;
        tile[threadIdx.y + i * 8][threadIdx.x] = b;
    }
    __syncthreads();
#pragma unroll
    for (int i = 0; i < 4; i++) {
        int d = d0 + threadIdx.y + i * 8;
        int p = p0 + threadIdx.x;
        xitb[(size_t)d * NPAT + p] = tile[threadIdx.x][threadIdx.y + i * 8];
    }
}

// colsum[d] = sum_p xi[p][d]  (fp32, deterministic)
__global__ void colsum_kernel(const float* __restrict__ xi, float* __restrict__ cs) {
    int d = blockIdx.x * blockDim.x + threadIdx.x;
    if (d < DIM) {
        float s = 0.f;
        for (int p = 0; p < NPAT; p++) s += xi[(size_t)p * DIM + d];
        cs[d] = s;
    }
}

// S[row] = P + sum_p E[row][p]  (deterministic block reduction)
__global__ void rowsum_kernel(const __nv_bfloat16* __restrict__ E, float* __restrict__ S) {
    int row = blockIdx.x;
    const __nv_bfloat16* e = E + (size_t)row * NPAT;
    float s = 0.f;
    for (int j = threadIdx.x; j < NPAT; j += 256) s += __bfloat162float(e[j]);
    __shared__ float red[256];
    red[threadIdx.x] = s;
    __syncthreads();
    for (int st = 128; st > 0; st >>= 1) {
        if (threadIdx.x < st) red[threadIdx.x] += red[threadIdx.x + st];
        __syncthreads();
    }
    if (threadIdx.x == 0) S[row] = (float)NPAT + red[0];
}

// ---------------- bf16 GEMM: C = A[M,K] @ B[N,K]^T, fp32 accum ----------------
// EPI 0: Cb = bf16(acc * (*beta))
// EPI 1: Cb = bf16(expm1f(acc))
// EPI 2: Cf = (acc + colsum[col]) / S[row]   (fp32 out)
#define BM 128
#define BN 128
#define BKT 32
#define SROW 40   // BKT + 8 pad -> conflict-free ldmatrix

__device__ __forceinline__ void cp16(uint32_t dst, const void* src) {
    asm volatile("cp.async.cg.shared.global [%0], [%1], 16;\n" :: "r"(dst), "l"(src));
}
__device__ __forceinline__ void ldm_x4(uint32_t* r, uint32_t addr) {
    asm volatile("ldmatrix.sync.aligned.m8n8.x4.shared.b16 {%0,%1,%2,%3}, [%4];\n"
                 : "=r"(r[0]), "=r"(r[1]), "=r"(r[2]), "=r"(r[3]) : "r"(addr));
}
__device__ __forceinline__ void mma_16816(float* c, const uint32_t* a, const uint32_t* b) {
    asm volatile("mma.sync.aligned.m16n8k16.row.col.f32.bf16.bf16.f32 "
                 "{%0,%1,%2,%3}, {%4,%5,%6,%7}, {%8,%9}, {%0,%1,%2,%3};\n"
                 : "+f"(c[0]), "+f"(c[1]), "+f"(c[2]), "+f"(c[3])
                 : "r"(a[0]), "r"(a[1]), "r"(a[2]), "r"(a[3]), "r"(b[0]), "r"(b[1]));
}

template <int EPI>
__global__ __launch_bounds__(256)
void gemm_bf16(const __nv_bfloat16* __restrict__ A, const __nv_bfloat16* __restrict__ B,
               void* __restrict__ Cv, int M, int N, int K,
               const float* __restrict__ beta,
               const float* __restrict__ colsum,
               const float* __restrict__ Ssum) {
    __shared__ __nv_bfloat16 sA[2][BM * SROW];
    __shared__ __nv_bfloat16 sB[2][BN * SROW];

    const int tid = threadIdx.x;
    const int lane = tid & 31;
    const int wid = tid >> 5;
    const int wm = wid & 1;   // 2 warps in M
    const int wn = wid >> 1;  // 4 warps in N
    const int mBase = blockIdx.y * BM;
    const int nBase = blockIdx.x * BN;

    uint32_t saA[2], saB[2];
    saA[0] = (uint32_t)__cvta_generic_to_shared(&sA[0][0]);
    saA[1] = (uint32_t)__cvta_generic_to_shared(&sA[1][0]);
    saB[0] = (uint32_t)__cvta_generic_to_shared(&sB[0][0]);
    saB[1] = (uint32_t)__cvta_generic_to_shared(&sB[1][0]);

    float acc[4][4][4];
#pragma unroll
    for (int i = 0; i < 4; i++)
#pragma unroll
        for (int j = 0; j < 4; j++)
#pragma unroll
            for (int k = 0; k < 4; k++) acc[i][j][k] = 0.f;

    const __nv_bfloat16* Ab = A + (size_t)mBase * K;
    const __nv_bfloat16* Bb = B + (size_t)nBase * K;

    const int lrow = tid >> 2;   // 0..63
    const int lkc  = tid & 3;    // 16B chunk within 32-elem row

    const int KT = K / BKT;

    // prologue: stage 0
    {
        const __nv_bfloat16* Ag = Ab;
        const __nv_bfloat16* Bg = Bb;
#pragma unroll
        for (int i = 0; i < 2; i++) {
            int r = lrow + i * 64;
            uint32_t off = (uint32_t)(r * SROW + lkc * 8) * 2;
            cp16(saA[0] + off, Ag + (size_t)r * K + lkc * 8);
            cp16(saB[0] + off, Bg + (size_t)r * K + lkc * 8);
        }
        asm volatile("cp.async.commit_group;\n");
    }

    for (int kt = 0; kt < KT; kt++) {
        bool more = (kt + 1 < KT);
        if (more) {
            int s = (kt + 1) & 1;
            const __nv_bfloat16* Ag = Ab + (size_t)(kt + 1) * BKT;
            const __nv_bfloat16* Bg = Bb + (size_t)(kt + 1) * BKT;
#pragma unroll
            for (int i = 0; i < 2; i++) {
                int r = lrow + i * 64;
                uint32_t off = (uint32_t)(r * SROW + lkc * 8) * 2;
                cp16(saA[s] + off, Ag + (size_t)r * K + lkc * 8);
                cp16(saB[s] + off, Bg + (size_t)r * K + lkc * 8);
            }
            asm volatile("cp.async.commit_group;\n");
            asm volatile("cp.async.wait_group 1;\n");
        } else {
            asm volatile("cp.async.wait_group 0;\n");
        }
        __syncthreads();

        const int s = kt & 1;
#pragma unroll
        for (int ks = 0; ks < 2; ks++) {
            uint32_t afr[4][4];
            uint32_t bfr[4][2];
#pragma unroll
            for (int mi = 0; mi < 4; mi++) {
                int arow = wm * 64 + mi * 16 + (lane & 15);
                int acol = ks * 16 + ((lane >> 4) << 3);
                uint32_t addr = saA[s] + (uint32_t)(arow * SROW + acol) * 2;
                ldm_x4(afr[mi], addr);
            }
#pragma unroll
            for (int pr = 0; pr < 2; pr++) {
                int grp = lane >> 3;
                int nrow = wn * 32 + pr * 16 + (lane & 7) + ((grp & 2) << 2);
                int kcol = ks * 16 + ((grp & 1) << 3);
                uint32_t addr = saB[s] + (uint32_t)(nrow * SROW + kcol) * 2;
                uint32_t r4[4];
                ldm_x4(r4, addr);
                bfr[pr * 2][0] = r4[0]; bfr[pr * 2][1] = r4[1];
                bfr[pr * 2 + 1][0] = r4[2]; bfr[pr * 2 + 1][1] = r4[3];
            }
#pragma unroll
            for (int mi = 0; mi < 4; mi++)
#pragma unroll
                for (int ni = 0; ni < 4; ni++)
                    mma_16816(acc[mi][ni], afr[mi], bfr[ni]);
        }
        __syncthreads();
    }

    // epilogue
    float betaV = 0.f;
    if (EPI == 0) betaV = *beta;

#pragma unroll
    for (int mi = 0; mi < 4; mi++) {
#pragma unroll
        for (int ni = 0; ni < 4; ni++) {
            int r0 = mBase + wm * 64 + mi * 16 + (lane >> 2);
            int c0 = nBase + wn * 32 + ni * 8 + (lane & 3) * 2;
            float* cc = acc[mi][ni];
#pragma unroll
            for (int h = 0; h < 2; h++) {
                int r = r0 + h * 8;
                float v0 = cc[2 * h];
                float v1 = cc[2 * h + 1];
                if (EPI == 0) {
                    __nv_bfloat16* Cb = (__nv_bfloat16*)Cv;
                    *reinterpret_cast<__nv_bfloat162*>(Cb + (size_t)r * N + c0) =
                        __floats2bfloat162_rn(v0 * betaV, v1 * betaV);
                } else if (EPI == 1) {
                    __nv_bfloat16* Cb = (__nv_bfloat16*)Cv;
                    *reinterpret_cast<__nv_bfloat162*>(Cb + (size_t)r * N + c0) =
                        __floats2bfloat162_rn(expm1f(v0), expm1f(v1));
                } else {
                    float* Cf = (float*)Cv;
                    float inv = 1.f / Ssum[r];
                    float o0 = (v0 + colsum[c0]) * inv;
                    float o1 = (v1 + colsum[c0 + 1]) * inv;
                    *reinterpret_cast<float2*>(Cf + (size_t)r * N + c0) = make_float2(o0, o1);
                }
            }
        }
    }
}

// ---------------- launch ----------------
extern "C" void kernel_launch(void* const* d_in, const int* in_sizes, int n_in,
                              void* d_out, int out_size) {
    const float* x    = (const float*)d_in[0];
    const float* wq   = (const float*)d_in[1];
    const float* xi   = (const float*)d_in[2];
    const float* beta = (const float*)d_in[3];
    float* out = (float*)d_out;

    void *xb, *wqb, *qb, *xib, *xitb, *Ebuf, *csv, *Sv;
    cudaGetSymbolAddress(&xb,   g_xb);
    cudaGetSymbolAddress(&wqb,  g_wqb);
    cudaGetSymbolAddress(&qb,   g_qb);
    cudaGetSymbolAddress(&xib,  g_xib);
    cudaGetSymbolAddress(&xitb, g_xitb);
    cudaGetSymbolAddress(&Ebuf, g_E);
    cudaGetSymbolAddress(&csv,  g_colsum);
    cudaGetSymbolAddress(&Sv,   g_S);

    // 1) convert x, w_q to bf16
    cvt4_kernel<<<(MTOK * DIM / 4 + 255) / 256, 256>>>((const float4*)x, (__nv_bfloat162*)xb, MTOK * DIM / 4);
    cvt4_kernel<<<(DIM * DIM / 4 + 255) / 256, 256>>>((const float4*)wq, (__nv_bfloat162*)wqb, DIM * DIM / 4);

    // 2) xi -> bf16 + transpose + fp32 colsum
    xi_prep_kernel<<<dim3(DIM / 32, NPAT / 32), dim3(32, 8)>>>(xi, (__nv_bfloat16*)xib, (__nv_bfloat16*)xitb);
    colsum_kernel<<<DIM / 256, 256>>>(xi, (float*)csv);

    // 3) qb = bf16(beta * x @ wq^T)
    gemm_bf16<0><<<dim3(DIM / BN, MTOK / BM), 256>>>(
        (const __nv_bfloat16*)xb, (const __nv_bfloat16*)wqb, qb,
        MTOK, DIM, DIM, beta, nullptr, nullptr);

    // 4) E = bf16(expm1(qb @ xib^T))
    gemm_bf16<1><<<dim3(NPAT / BN, MTOK / BM), 256>>>(
        (const __nv_bfloat16*)qb, (const __nv_bfloat16*)xib, Ebuf,
        MTOK, NPAT, DIM, nullptr, nullptr, nullptr);

    // 5) S[row] = P + sum_p E
    rowsum_kernel<<<MTOK, 256>>>((const __nv_bfloat16*)Ebuf, (float*)Sv);

    // 6) out = (E @ xitb^T + colsum) / S
    gemm_bf16<2><<<dim3(DIM / BN, MTOK / BM), 256>>>(
        (const __nv_bfloat16*)Ebuf, (const __nv_bfloat16*)xitb, d_out,
        MTOK, DIM, NPAT, nullptr, (const float*)csv, (const float*)Sv);
    (void)in_sizes; (void)n_in; (void)out; (void)out_size;
}

// round 2
// speedup vs baseline: 1.0914x; 1.0914x over previous
#include <cuda_runtime.h>
#include <cuda_bf16.h>
#include <cstdint>
#include <math.h>

// ---------------- problem constants ----------------
#define MTOK 8192      // B*S tokens
#define DIM  1024
#define NPAT 8192
#define NBX  (NPAT / 128)   // 64 column-blocks in the E GEMM

// ---------------- scratch (static device arrays; no allocation) ----------------
__device__ __nv_bfloat16 g_xb  [(size_t)MTOK * DIM];    // x in bf16
__device__ __nv_bfloat16 g_wqb [(size_t)DIM * DIM];     // w_q in bf16 [out][in]
__device__ __nv_bfloat16 g_qb  [(size_t)MTOK * DIM];    // beta * q in bf16
__device__ __nv_bfloat16 g_xib [(size_t)NPAT * DIM];    // xi in bf16 [P][D]
__device__ __nv_bfloat16 g_xitb[(size_t)DIM * NPAT];    // xi^T in bf16 [D][P]
__device__ __nv_bfloat16 g_E   [(size_t)MTOK * NPAT];   // expm1(logits) in bf16 (128MB)
__device__ float g_cspart[32][DIM];                      // colsum partials
__device__ float g_colsum[DIM];                          // sum_p xi[p][d] (fp32)
__device__ float g_rowpart[NBX][MTOK];                   // per-colblock row sums of E
__device__ float g_S[MTOK];                              // P + sum_p E[row][p]

// ---------------- small prep kernels ----------------
__global__ void cvt4_kernel(const float4* __restrict__ in, __nv_bfloat162* __restrict__ out, int n4) {
    int i = blockIdx.x * blockDim.x + threadIdx.x;
    if (i < n4) {
        float4 v = in[i];
        out[2 * i]     = __floats2bfloat162_rn(v.x, v.y);
        out[2 * i + 1] = __floats2bfloat162_rn(v.z, v.w);
    }
}

// xi -> bf16 [P][D] and transposed bf16 [D][P] via smem tiles
__global__ void xi_prep_kernel(const float* __restrict__ xi,
                               __nv_bfloat16* __restrict__ xib,
                               __nv_bfloat16* __restrict__ xitb) {
    __shared__ __nv_bfloat16 tile[32][33];
    int d0 = blockIdx.x * 32;
    int p0 = blockIdx.y * 32;
#pragma unroll
    for (int i = 0; i < 4; i++) {
        int p = p0 + threadIdx.y + i * 8;
        int d = d0 + threadIdx.x;
        float v = xi[(size_t)p * DIM + d];
        __nv_bfloat16 b = __float2bfloat16(v);
        xib[(size_t)p * DIM + d] = b;
        tile[threadIdx.y + i * 8][threadIdx.x] = b;
    }
    __syncthreads();
#pragma unroll
    for (int i = 0; i < 4; i++) {
        int d = d0 + threadIdx.y + i * 8;
        int p = p0 + threadIdx.x;
        xitb[(size_t)d * NPAT + p] = tile[threadIdx.x][threadIdx.y + i * 8];
    }
}

// colsum partials: block (bx, by) sums patterns [by*256, by*256+256) for cols bx*256..
__global__ void colsum_part_kernel(const float* __restrict__ xi, float* __restrict__ part) {
    int d = blockIdx.x * 256 + threadIdx.x;
    int p0 = blockIdx.y * 256;
    float s = 0.f;
#pragma unroll 4
    for (int p = p0; p < p0 + 256; p++) s += xi[(size_t)p * DIM + d];
    part[blockIdx.y * DIM + d] = s;
}
__global__ void colsum_final_kernel(const float* __restrict__ part, float* __restrict__ cs) {
    int d = blockIdx.x * 256 + threadIdx.x;
    float s = 0.f;
#pragma unroll
    for (int b = 0; b < 32; b++) s += part[b * DIM + d];
    cs[d] = s;
}

// S[row] = P + sum over 64 column-block partials (2MB read, deterministic)
__global__ void rowsum_reduce_kernel(const float* __restrict__ rowpart, float* __restrict__ S) {
    int row = blockIdx.x * 256 + threadIdx.x;
    float s = 0.f;
#pragma unroll
    for (int b = 0; b < NBX; b++) s += rowpart[(size_t)b * MTOK + row];
    S[row] = (float)NPAT + s;
}

// ---------------- bf16 GEMM: C = A[M,K] @ B[N,K]^T, fp32 accum ----------------
// EPI 0: Cb = bf16(acc * (*beta))
// EPI 1: Cb = bf16(expm1f(acc)); also emit per-block row sums of expm1 -> rowpart
// EPI 2: Cf = (acc + colsum[col]) / S[row]   (fp32 out)
#define BM 128
#define BN 128
#define BKT 32
#define SROW 40   // BKT + 8 pad -> conflict-free ldmatrix

__device__ __forceinline__ void cp16(uint32_t dst, const void* src) {
    asm volatile("cp.async.cg.shared.global [%0], [%1], 16;\n" :: "r"(dst), "l"(src));
}
__device__ __forceinline__ void ldm_x4(uint32_t* r, uint32_t addr) {
    asm volatile("ldmatrix.sync.aligned.m8n8.x4.shared.b16 {%0,%1,%2,%3}, [%4];\n"
                 : "=r"(r[0]), "=r"(r[1]), "=r"(r[2]), "=r"(r[3]) : "r"(addr));
}
__device__ __forceinline__ void mma_16816(float* c, const uint32_t* a, const uint32_t* b) {
    asm volatile("mma.sync.aligned.m16n8k16.row.col.f32.bf16.bf16.f32 "
                 "{%0,%1,%2,%3}, {%4,%5,%6,%7}, {%8,%9}, {%0,%1,%2,%3};\n"
                 : "+f"(c[0]), "+f"(c[1]), "+f"(c[2]), "+f"(c[3])
                 : "r"(a[0]), "r"(a[1]), "r"(a[2]), "r"(a[3]), "r"(b[0]), "r"(b[1]));
}

template <int EPI>
__global__ __launch_bounds__(256)
void gemm_bf16(const __nv_bfloat16* __restrict__ A, const __nv_bfloat16* __restrict__ B,
               void* __restrict__ Cv, int M, int N, int K,
               const float* __restrict__ beta,
               const float* __restrict__ colsum,
               const float* __restrict__ Ssum,
               float* __restrict__ rowpart) {
    __shared__ __nv_bfloat16 sA[2][BM * SROW];
    __shared__ __nv_bfloat16 sB[2][BN * SROW];
    __shared__ float srow[4][BM];   // only used by EPI==1

    const int tid = threadIdx.x;
    const int lane = tid & 31;
    const int wid = tid >> 5;
    const int wm = wid & 1;   // 2 warps in M
    const int wn = wid >> 1;  // 4 warps in N
    const int mBase = blockIdx.y * BM;
    const int nBase = blockIdx.x * BN;

    uint32_t saA[2], saB[2];
    saA[0] = (uint32_t)__cvta_generic_to_shared(&sA[0][0]);
    saA[1] = (uint32_t)__cvta_generic_to_shared(&sA[1][0]);
    saB[0] = (uint32_t)__cvta_generic_to_shared(&sB[0][0]);
    saB[1] = (uint32_t)__cvta_generic_to_shared(&sB[1][0]);

    float acc[4][4][4];
#pragma unroll
    for (int i = 0; i < 4; i++)
#pragma unroll
        for (int j = 0; j < 4; j++)
#pragma unroll
            for (int k = 0; k < 4; k++) acc[i][j][k] = 0.f;

    const __nv_bfloat16* Ab = A + (size_t)mBase * K;
    const __nv_bfloat16* Bb = B + (size_t)nBase * K;

    const int lrow = tid >> 2;   // 0..63
    const int lkc  = tid & 3;    // 16B chunk within 32-elem row

    const int KT = K / BKT;

    // prologue: stage 0
    {
#pragma unroll
        for (int i = 0; i < 2; i++) {
            int r = lrow + i * 64;
            uint32_t off = (uint32_t)(r * SROW + lkc * 8) * 2;
            cp16(saA[0] + off, Ab + (size_t)r * K + lkc * 8);
            cp16(saB[0] + off, Bb + (size_t)r * K + lkc * 8);
        }
        asm volatile("cp.async.commit_group;\n");
    }

    for (int kt = 0; kt < KT; kt++) {
        bool more = (kt + 1 < KT);
        if (more) {
            int s = (kt + 1) & 1;
            const __nv_bfloat16* Ag = Ab + (size_t)(kt + 1) * BKT;
            const __nv_bfloat16* Bg = Bb + (size_t)(kt + 1) * BKT;
#pragma unroll
            for (int i = 0; i < 2; i++) {
                int r = lrow + i * 64;
                uint32_t off = (uint32_t)(r * SROW + lkc * 8) * 2;
                cp16(saA[s] + off, Ag + (size_t)r * K + lkc * 8);
                cp16(saB[s] + off, Bg + (size_t)r * K + lkc * 8);
            }
            asm volatile("cp.async.commit_group;\n");
            asm volatile("cp.async.wait_group 1;\n");
        } else {
            asm volatile("cp.async.wait_group 0;\n");
        }
        __syncthreads();

        const int s = kt & 1;
#pragma unroll
        for (int ks = 0; ks < 2; ks++) {
            uint32_t afr[4][4];
            uint32_t bfr[4][2];
#pragma unroll
            for (int mi = 0; mi < 4; mi++) {
                int arow = wm * 64 + mi * 16 + (lane & 15);
                int acol = ks * 16 + ((lane >> 4) << 3);
                uint32_t addr = saA[s] + (uint32_t)(arow * SROW + acol) * 2;
                ldm_x4(afr[mi], addr);
            }
#pragma unroll
            for (int pr = 0; pr < 2; pr++) {
                int grp = lane >> 3;
                int nrow = wn * 32 + pr * 16 + (lane & 7) + ((grp & 2) << 2);
                int kcol = ks * 16 + ((grp & 1) << 3);
                uint32_t addr = saB[s] + (uint32_t)(nrow * SROW + kcol) * 2;
                uint32_t r4[4];
                ldm_x4(r4, addr);
                bfr[pr * 2][0] = r4[0]; bfr[pr * 2][1] = r4[1];
                bfr[pr * 2 + 1][0] = r4[2]; bfr[pr * 2 + 1][1] = r4[3];
            }
#pragma unroll
            for (int mi = 0; mi < 4; mi++)
#pragma unroll
                for (int ni = 0; ni < 4; ni++)
                    mma_16816(acc[mi][ni], afr[mi], bfr[ni]);
        }
        __syncthreads();
    }

    // epilogue
    float betaV = 0.f;
    if (EPI == 0) betaV = *beta;

    float rloc[4][2];   // per-thread partial row sums (EPI==1)
    if (EPI == 1) {
#pragma unroll
        for (int mi = 0; mi < 4; mi++) { rloc[mi][0] = 0.f; rloc[mi][1] = 0.f; }
    }

#pragma unroll
    for (int mi = 0; mi < 4; mi++) {
#pragma unroll
        for (int ni = 0; ni < 4; ni++) {
            int r0 = mBase + wm * 64 + mi * 16 + (lane >> 2);
            int c0 = nBase + wn * 32 + ni * 8 + (lane & 3) * 2;
            float* cc = acc[mi][ni];
#pragma unroll
            for (int h = 0; h < 2; h++) {
                int r = r0 + h * 8;
                float v0 = cc[2 * h];
                float v1 = cc[2 * h + 1];
                if (EPI == 0) {
                    __nv_bfloat16* Cb = (__nv_bfloat16*)Cv;
                    *reinterpret_cast<__nv_bfloat162*>(Cb + (size_t)r * N + c0) =
                        __floats2bfloat162_rn(v0 * betaV, v1 * betaV);
                } else if (EPI == 1) {
                    float e0 = expm1f(v0);
                    float e1 = expm1f(v1);
                    rloc[mi][h] += e0 + e1;
                    __nv_bfloat16* Cb = (__nv_bfloat16*)Cv;
                    *reinterpret_cast<__nv_bfloat162*>(Cb + (size_t)r * N + c0) =
                        __floats2bfloat162_rn(e0, e1);
                } else {
                    float* Cf = (float*)Cv;
                    float inv = 1.f / Ssum[r];
                    float o0 = (v0 + colsum[c0]) * inv;
                    float o1 = (v1 + colsum[c0 + 1]) * inv;
                    *reinterpret_cast<float2*>(Cf + (size_t)r * N + c0) = make_float2(o0, o1);
                }
            }
        }
    }

    if (EPI == 1) {
        // reduce across the 4 lanes sharing each row (lane&3 varies), then across wn
#pragma unroll
        for (int mi = 0; mi < 4; mi++) {
#pragma unroll
            for (int h = 0; h < 2; h++) {
                float v = rloc[mi][h];
                v += __shfl_xor_sync(0xffffffffu, v, 1);
                v += __shfl_xor_sync(0xffffffffu, v, 2);
                if ((lane & 3) == 0) {
                    int rloc_idx = wm * 64 + mi * 16 + h * 8 + (lane >> 2);
                    srow[wn][rloc_idx] = v;   // distinct (wn, row) per writer
                }
            }
        }
        __syncthreads();
        if (tid < BM) {
            float s = srow[0][tid] + srow[1][tid] + srow[2][tid] + srow[3][tid];
            rowpart[(size_t)blockIdx.x * MTOK + (mBase + tid)] = s;
        }
    }
}

// ---------------- launch ----------------
extern "C" void kernel_launch(void* const* d_in, const int* in_sizes, int n_in,
                              void* d_out, int out_size) {
    const float* x    = (const float*)d_in[0];
    const float* wq   = (const float*)d_in[1];
    const float* xi   = (const float*)d_in[2];
    const float* beta = (const float*)d_in[3];

    void *xb, *wqb, *qb, *xib, *xitb, *Ebuf, *cspart, *csv, *rowpart, *Sv;
    cudaGetSymbolAddress(&xb,      g_xb);
    cudaGetSymbolAddress(&wqb,     g_wqb);
    cudaGetSymbolAddress(&qb,      g_qb);
    cudaGetSymbolAddress(&xib,     g_xib);
    cudaGetSymbolAddress(&xitb,    g_xitb);
    cudaGetSymbolAddress(&Ebuf,    g_E);
    cudaGetSymbolAddress(&cspart,  g_cspart);
    cudaGetSymbolAddress(&csv,     g_colsum);
    cudaGetSymbolAddress(&rowpart, g_rowpart);
    cudaGetSymbolAddress(&Sv,      g_S);

    // 1) convert x, w_q to bf16
    cvt4_kernel<<<(MTOK * DIM / 4 + 255) / 256, 256>>>((const float4*)x, (__nv_bfloat162*)xb, MTOK * DIM / 4);
    cvt4_kernel<<<(DIM * DIM / 4 + 255) / 256, 256>>>((const float4*)wq, (__nv_bfloat162*)wqb, DIM * DIM / 4);

    // 2) xi -> bf16 + transpose + parallel fp32 colsum
    xi_prep_kernel<<<dim3(DIM / 32, NPAT / 32), dim3(32, 8)>>>(xi, (__nv_bfloat16*)xib, (__nv_bfloat16*)xitb);
    colsum_part_kernel<<<dim3(DIM / 256, 32), 256>>>(xi, (float*)cspart);
    colsum_final_kernel<<<DIM / 256, 256>>>((const float*)cspart, (float*)csv);

    // 3) qb = bf16(beta * x @ wq^T)
    gemm_bf16<0><<<dim3(DIM / BN, MTOK / BM), 256>>>(
        (const __nv_bfloat16*)xb, (const __nv_bfloat16*)wqb, qb,
        MTOK, DIM, DIM, beta, nullptr, nullptr, nullptr);

    // 4) E = bf16(expm1(qb @ xib^T)) + fused per-block row sums
    gemm_bf16<1><<<dim3(NPAT / BN, MTOK / BM), 256>>>(
        (const __nv_bfloat16*)qb, (const __nv_bfloat16*)xib, Ebuf,
        MTOK, NPAT, DIM, nullptr, nullptr, nullptr, (float*)rowpart);

    // 5) S[row] = P + sum of 64 partials (2MB instead of 128MB)
    rowsum_reduce_kernel<<<MTOK / 256, 256>>>((const float*)rowpart, (float*)Sv);

    // 6) out = (E @ xitb^T + colsum) / S
    gemm_bf16<2><<<dim3(DIM / BN, MTOK / BM), 256>>>(
        (const __nv_bfloat16*)Ebuf, (const __nv_bfloat16*)xitb, d_out,
        MTOK, DIM, NPAT, nullptr, (const float*)csv, (const float*)Sv, nullptr);
    (void)in_sizes; (void)n_in; (void)out_size;
}